// round 2
// baseline (speedup 1.0000x reference)
#include <cuda_runtime.h>
#include <cuda_bf16.h>
#include <math.h>

// Problem constants
#define BATCH 4
#define SEQ   2048
#define DIM   768
#define HEADS 12
#define DHEAD 64
#define INNER 768
#define ROWS  (BATCH * SEQ)        // 8192
#define QKV_N (3 * INNER)          // 2304

// Scratch (allocation-free: __device__ globals)
__device__ __align__(256) float g_xn[ROWS * DIM];       // 25 MB
__device__ __align__(256) float g_qkv[ROWS * QKV_N];    // 75.5 MB
__device__ __align__(256) float g_attn[ROWS * INNER];   // 25 MB

// ---------------------------------------------------------------------------
// Kernel 1: LayerNorm, one block per row (768 elems, 256 threads x 3)
// ---------------------------------------------------------------------------
__global__ __launch_bounds__(256) void ln_kernel(
    const float* __restrict__ x, const float* __restrict__ g,
    const float* __restrict__ b, float* __restrict__ xn)
{
    const int row = blockIdx.x;
    const int tid = threadIdx.x;
    const float* xr = x + (size_t)row * DIM;

    float v0 = xr[tid];
    float v1 = xr[tid + 256];
    float v2 = xr[tid + 512];
    float s  = v0 + v1 + v2;
    float ss = v0 * v0 + v1 * v1 + v2 * v2;

    #pragma unroll
    for (int m = 16; m; m >>= 1) {
        s  += __shfl_xor_sync(0xffffffffu, s, m);
        ss += __shfl_xor_sync(0xffffffffu, ss, m);
    }
    __shared__ float shs[8], shss[8], stat[2];
    const int w = tid >> 5, l = tid & 31;
    if (l == 0) { shs[w] = s; shss[w] = ss; }
    __syncthreads();
    if (tid == 0) {
        float S = 0.f, SS = 0.f;
        #pragma unroll
        for (int i = 0; i < 8; i++) { S += shs[i]; SS += shss[i]; }
        float mean = S * (1.f / DIM);
        float var  = SS * (1.f / DIM) - mean * mean;
        stat[0] = mean;
        stat[1] = rsqrtf(var + 1e-5f);
    }
    __syncthreads();
    const float mean = stat[0], rstd = stat[1];
    float* xo = xn + (size_t)row * DIM;
    xo[tid]       = (v0 - mean) * rstd * g[tid]       + b[tid];
    xo[tid + 256] = (v1 - mean) * rstd * g[tid + 256] + b[tid + 256];
    xo[tid + 512] = (v2 - mean) * rstd * g[tid + 512] + b[tid + 512];
}

// ---------------------------------------------------------------------------
// Kernel 2/4: SGEMM C = A[M,K] @ B[K,N] + bias, 128x128x8 tile, 8x8/thread
// ---------------------------------------------------------------------------
__global__ __launch_bounds__(256) void sgemm_bias(
    const float* __restrict__ A, const float* __restrict__ B,
    const float* __restrict__ bias, float* __restrict__ C,
    int M, int N, int K)
{
    __shared__ float As[8][128];
    __shared__ float Bs[8][128];

    const int tid = threadIdx.x;
    const int tx = tid & 15;    // 16 thread-cols
    const int ty = tid >> 4;    // 16 thread-rows
    const int bx = blockIdx.x;
    const int by = blockIdx.y;

    const float* Ab = A + (size_t)by * 128 * K;
    const float* Bb = B + (size_t)bx * 128;

    const int aRow = tid >> 1;          // 0..127
    const int aK   = (tid & 1) * 4;     // 0 or 4
    const int bRow = tid >> 5;          // 0..7
    const int bCol = (tid & 31) * 4;    // 0..124

    float acc[8][8] = {};
    float ra[8], rb[8];

    for (int k0 = 0; k0 < K; k0 += 8) {
        float4 av = *(const float4*)(Ab + (size_t)aRow * K + k0 + aK);
        float4 bv = *(const float4*)(Bb + (size_t)(k0 + bRow) * N + bCol);
        As[aK + 0][aRow] = av.x;
        As[aK + 1][aRow] = av.y;
        As[aK + 2][aRow] = av.z;
        As[aK + 3][aRow] = av.w;
        *(float4*)(&Bs[bRow][bCol]) = bv;
        __syncthreads();
        #pragma unroll
        for (int k = 0; k < 8; k++) {
            #pragma unroll
            for (int i = 0; i < 8; i++) ra[i] = As[k][ty * 8 + i];
            #pragma unroll
            for (int j = 0; j < 8; j++) rb[j] = Bs[k][tx * 8 + j];
            #pragma unroll
            for (int i = 0; i < 8; i++)
                #pragma unroll
                for (int j = 0; j < 8; j++)
                    acc[i][j] += ra[i] * rb[j];
        }
        __syncthreads();
    }

    #pragma unroll
    for (int i = 0; i < 8; i++) {
        size_t row = (size_t)by * 128 + ty * 8 + i;
        float* Crow = C + row * N + bx * 128 + tx * 8;
        const float* brow = bias + bx * 128 + tx * 8;
        #pragma unroll
        for (int j = 0; j < 8; j += 4) {
            float4 v;
            v.x = acc[i][j + 0] + brow[j + 0];
            v.y = acc[i][j + 1] + brow[j + 1];
            v.z = acc[i][j + 2] + brow[j + 2];
            v.w = acc[i][j + 3] + brow[j + 3];
            *(float4*)(Crow + j) = v;
        }
    }
}

// ---------------------------------------------------------------------------
// Kernel 3: flash attention. BR=BC=64, d=64, online softmax, fp32 exact.
// grid = (32 q-tiles, 48 batch*head), 256 threads (16x16, 4x4 micro-tile).
// ---------------------------------------------------------------------------
__global__ __launch_bounds__(256) void flash_kernel(
    const float* __restrict__ qkv, float* __restrict__ out)
{
    __shared__ float Qs[64][64];  // [d][qrow], pre-scaled
    __shared__ float Ks[64][64];  // [d][key]
    __shared__ float Vs[64][64];  // [key][d]
    __shared__ float Ps[64][64];  // [key][qrow]

    const int tid = threadIdx.x;
    const int tx = tid & 15;
    const int ty = tid >> 4;
    const int qt = blockIdx.x;        // 0..31 query tile
    const int bh = blockIdx.y;        // 0..47
    const int bb = bh / HEADS, h = bh % HEADS;

    const float* base = qkv + (size_t)bb * SEQ * QKV_N;
    const float* qb = base + h * DHEAD;
    const float* kb = base + INNER + h * DHEAD;
    const float* vb = base + 2 * INNER + h * DHEAD;

    // load Q tile transposed + scaled by 1/sqrt(64)
    for (int it = tid; it < 1024; it += 256) {
        int r  = it >> 4;
        int d4 = (it & 15) << 2;
        float4 qv = *(const float4*)(qb + (size_t)(qt * 64 + r) * QKV_N + d4);
        Qs[d4 + 0][r] = qv.x * 0.125f;
        Qs[d4 + 1][r] = qv.y * 0.125f;
        Qs[d4 + 2][r] = qv.z * 0.125f;
        Qs[d4 + 3][r] = qv.w * 0.125f;
    }

    float m[4], l[4], o[4][4];
    #pragma unroll
    for (int i = 0; i < 4; i++) {
        m[i] = -1e30f; l[i] = 0.f;
        #pragma unroll
        for (int j = 0; j < 4; j++) o[i][j] = 0.f;
    }

    for (int t = 0; t < SEQ / 64; t++) {
        __syncthreads();  // guard K/V/P overwrite vs previous iter readers
        for (int it = tid; it < 1024; it += 256) {
            int r  = it >> 4;
            int d4 = (it & 15) << 2;
            size_t roff = (size_t)(t * 64 + r) * QKV_N + d4;
            float4 kv = *(const float4*)(kb + roff);
            Ks[d4 + 0][r] = kv.x; Ks[d4 + 1][r] = kv.y;
            Ks[d4 + 2][r] = kv.z; Ks[d4 + 3][r] = kv.w;
            float4 vv = *(const float4*)(vb + roff);
            *(float4*)&Vs[r][d4] = vv;
        }
        __syncthreads();

        // S = Q @ K^T (4x4 per thread)
        float s[4][4] = {};
        #pragma unroll 8
        for (int kk = 0; kk < 64; kk++) {
            float qr[4], kr[4];
            #pragma unroll
            for (int i = 0; i < 4; i++) qr[i] = Qs[kk][ty * 4 + i];
            #pragma unroll
            for (int j = 0; j < 4; j++) kr[j] = Ks[kk][tx * 4 + j];
            #pragma unroll
            for (int i = 0; i < 4; i++)
                #pragma unroll
                for (int j = 0; j < 4; j++)
                    s[i][j] += qr[i] * kr[j];
        }

        // online softmax per row (reduce across 16 tx lanes)
        #pragma unroll
        for (int i = 0; i < 4; i++) {
            float tm = s[i][0];
            #pragma unroll
            for (int j = 1; j < 4; j++) tm = fmaxf(tm, s[i][j]);
            #pragma unroll
            for (int msk = 8; msk; msk >>= 1)
                tm = fmaxf(tm, __shfl_xor_sync(0xffffffffu, tm, msk));
            float mn = fmaxf(m[i], tm);
            float alpha = __expf(m[i] - mn);
            m[i] = mn;
            float rs = 0.f;
            #pragma unroll
            for (int j = 0; j < 4; j++) {
                s[i][j] = __expf(s[i][j] - mn);
                rs += s[i][j];
            }
            #pragma unroll
            for (int msk = 8; msk; msk >>= 1)
                rs += __shfl_xor_sync(0xffffffffu, rs, msk);
            l[i] = l[i] * alpha + rs;
            #pragma unroll
            for (int j = 0; j < 4; j++) o[i][j] *= alpha;
        }

        // P transposed to smem
        #pragma unroll
        for (int i = 0; i < 4; i++)
            #pragma unroll
            for (int j = 0; j < 4; j++)
                Ps[tx * 4 + j][ty * 4 + i] = s[i][j];
        __syncthreads();

        // O += P @ V
        #pragma unroll 8
        for (int kk = 0; kk < 64; kk++) {
            float pr[4], vr[4];
            #pragma unroll
            for (int i = 0; i < 4; i++) pr[i] = Ps[kk][ty * 4 + i];
            #pragma unroll
            for (int j = 0; j < 4; j++) vr[j] = Vs[kk][tx * 4 + j];
            #pragma unroll
            for (int i = 0; i < 4; i++)
                #pragma unroll
                for (int j = 0; j < 4; j++)
                    o[i][j] += pr[i] * vr[j];
        }
    }

    // normalize and write out in [b, n, h*64 + d] layout
    #pragma unroll
    for (int i = 0; i < 4; i++) {
        float inv = 1.f / l[i];
        size_t n = (size_t)bb * SEQ + qt * 64 + ty * 4 + i;
        float4 v;
        v.x = o[i][0] * inv;
        v.y = o[i][1] * inv;
        v.z = o[i][2] * inv;
        v.w = o[i][3] * inv;
        *(float4*)(out + n * INNER + h * DHEAD + tx * 4) = v;
    }
}

// ---------------------------------------------------------------------------
extern "C" void kernel_launch(void* const* d_in, const int* in_sizes, int n_in,
                              void* d_out, int out_size)
{
    const float* x     = (const float*)d_in[0];
    const float* ln_g  = (const float*)d_in[1];
    const float* ln_b  = (const float*)d_in[2];
    const float* W_qkv = (const float*)d_in[3];
    const float* b_qkv = (const float*)d_in[4];
    const float* W_out = (const float*)d_in[5];
    const float* b_out = (const float*)d_in[6];
    float* out = (float*)d_out;

    float *xn, *qkv, *attn;
    cudaGetSymbolAddress((void**)&xn,   g_xn);
    cudaGetSymbolAddress((void**)&qkv,  g_qkv);
    cudaGetSymbolAddress((void**)&attn, g_attn);

    // 1) LayerNorm
    ln_kernel<<<ROWS, 256>>>(x, ln_g, ln_b, xn);

    // 2) QKV projection: [8192,768] @ [768,2304] + b
    sgemm_bias<<<dim3(QKV_N / 128, ROWS / 128), 256>>>(
        xn, W_qkv, b_qkv, qkv, ROWS, QKV_N, DIM);

    // 3) attention
    flash_kernel<<<dim3(SEQ / 64, BATCH * HEADS), 256>>>(qkv, attn);

    // 4) output projection: [8192,768] @ [768,768] + b
    sgemm_bias<<<dim3(DIM / 128, ROWS / 128), 256>>>(
        attn, W_out, b_out, out, ROWS, DIM, INNER);
}

// round 5
// speedup vs baseline: 3.4374x; 3.4374x over previous
#include <cuda_runtime.h>
#include <cstdint>
#include <math.h>

// Problem constants
#define BATCH 4
#define SEQ   2048
#define DIM   768
#define HEADS 12
#define DHEAD 64
#define INNER 768
#define ROWS  (BATCH * SEQ)        // 8192
#define QKV_N (3 * INNER)          // 2304

// Scratch (allocation-free: __device__ globals)
__device__ __align__(256) float g_xn[ROWS * DIM];
__device__ __align__(256) float g_qkv[ROWS * QKV_N];
__device__ __align__(256) float g_attn[ROWS * INNER];
__device__ __align__(256) float g_wtq[QKV_N * DIM];   // W_qkv^T  [N,K]
__device__ __align__(256) float g_wto[DIM * INNER];   // W_out^T  [N,K]

// ---------------------------------------------------------------------------
// tf32 helpers (sm_80+ mma.sync — compiles for plain compute_103)
// ---------------------------------------------------------------------------
__device__ __forceinline__ float tf32r(float x) {
    float r;
    asm("cvt.rna.tf32.f32 %0, %1;" : "=f"(r) : "f"(x));
    return r;
}

__device__ __forceinline__ void mma8(float c[4],
                                     uint32_t a0, uint32_t a1, uint32_t a2, uint32_t a3,
                                     uint32_t b0, uint32_t b1) {
    asm volatile(
        "mma.sync.aligned.m16n8k8.row.col.f32.tf32.tf32.f32 "
        "{%0,%1,%2,%3}, {%4,%5,%6,%7}, {%8,%9}, {%0,%1,%2,%3};"
        : "+f"(c[0]), "+f"(c[1]), "+f"(c[2]), "+f"(c[3])
        : "r"(a0), "r"(a1), "r"(a2), "r"(a3), "r"(b0), "r"(b1));
}

// ---------------------------------------------------------------------------
// Kernel 0: transpose W[K,N] -> Wt[N,K]
// ---------------------------------------------------------------------------
__global__ __launch_bounds__(256) void transpose_k(
    const float* __restrict__ W, float* __restrict__ Wt, int R, int Ccols)
{
    __shared__ float t[32][33];
    const int c0 = blockIdx.x * 32, r0 = blockIdx.y * 32;
    const int x = threadIdx.x & 31, y = threadIdx.x >> 5;
    #pragma unroll
    for (int i = 0; i < 32; i += 8)
        t[y + i][x] = W[(size_t)(r0 + y + i) * Ccols + c0 + x];
    __syncthreads();
    #pragma unroll
    for (int i = 0; i < 32; i += 8)
        Wt[(size_t)(c0 + y + i) * R + r0 + x] = t[x][y + i];
}

// ---------------------------------------------------------------------------
// Kernel 1: LayerNorm, one block per row
// ---------------------------------------------------------------------------
__global__ __launch_bounds__(256) void ln_kernel(
    const float* __restrict__ x, const float* __restrict__ g,
    const float* __restrict__ b, float* __restrict__ xn)
{
    const int row = blockIdx.x;
    const int tid = threadIdx.x;
    const float* xr = x + (size_t)row * DIM;

    float v0 = xr[tid];
    float v1 = xr[tid + 256];
    float v2 = xr[tid + 512];
    float s  = v0 + v1 + v2;
    float ss = v0 * v0 + v1 * v1 + v2 * v2;

    #pragma unroll
    for (int m = 16; m; m >>= 1) {
        s  += __shfl_xor_sync(0xffffffffu, s, m);
        ss += __shfl_xor_sync(0xffffffffu, ss, m);
    }
    __shared__ float shs[8], shss[8], stat[2];
    const int w = tid >> 5, l = tid & 31;
    if (l == 0) { shs[w] = s; shss[w] = ss; }
    __syncthreads();
    if (tid == 0) {
        float S = 0.f, SS = 0.f;
        #pragma unroll
        for (int i = 0; i < 8; i++) { S += shs[i]; SS += shss[i]; }
        float mean = S * (1.f / DIM);
        float var  = SS * (1.f / DIM) - mean * mean;
        stat[0] = mean;
        stat[1] = rsqrtf(var + 1e-5f);
    }
    __syncthreads();
    const float mean = stat[0], rstd = stat[1];
    float* xo = xn + (size_t)row * DIM;
    xo[tid]       = (v0 - mean) * rstd * g[tid]       + b[tid];
    xo[tid + 256] = (v1 - mean) * rstd * g[tid + 256] + b[tid + 256];
    xo[tid + 512] = (v2 - mean) * rstd * g[tid + 512] + b[tid + 512];
}

// ---------------------------------------------------------------------------
// Kernel 2/4: tf32 mma GEMM.  C[M,N] = A[M,K] @ Bt[N,K]^T + bias
// 128x128 block, 256 threads = 8 warps (4m x 2n), each warp 32x64.
// K-chunk 32, register prefetch.  SMEM stride 36 (≡4 mod 32) => the
// fragment address pattern 4*(lane/4)+(lane&3) is bank-conflict-free.
// ---------------------------------------------------------------------------
#define TSTR 36

__global__ __launch_bounds__(256) void gemm_mma(
    const float* __restrict__ A, const float* __restrict__ Bt,
    const float* __restrict__ bias, float* __restrict__ C, int N, int K)
{
    __shared__ float As[128][TSTR];
    __shared__ float Bs[128][TSTR];

    const int tid  = threadIdx.x;
    const int lane = tid & 31;
    const int wid  = tid >> 5;
    const int wm = (wid >> 1) * 32;   // warp m-offset (0,32,64,96)
    const int wn = (wid & 1) * 64;    // warp n-offset (0,64)
    const int qr = lane >> 2;         // 0..7
    const int qc = lane & 3;          // 0..3
    const int bx = blockIdx.x, by = blockIdx.y;

    const int lrow = tid >> 3;        // 0..31  (+i*32)
    const int lcol = (tid & 7) * 4;   // 0..28

    const float* Ab = A  + (size_t)by * 128 * K;
    const float* Bb = Bt + (size_t)bx * 128 * K;

    float4 pa[4], pb[4];
    #pragma unroll
    for (int i = 0; i < 4; i++) {
        pa[i] = *(const float4*)(Ab + (size_t)(lrow + i * 32) * K + lcol);
        pb[i] = *(const float4*)(Bb + (size_t)(lrow + i * 32) * K + lcol);
    }

    float acc[2][8][4];
    #pragma unroll
    for (int mi = 0; mi < 2; mi++)
        #pragma unroll
        for (int ni = 0; ni < 8; ni++)
            #pragma unroll
            for (int j = 0; j < 4; j++) acc[mi][ni][j] = 0.f;

    const int NC = K / 32;
    for (int kc = 0; kc < NC; kc++) {
        #pragma unroll
        for (int i = 0; i < 4; i++) {
            const int r = lrow + i * 32;
            As[r][lcol + 0] = tf32r(pa[i].x);
            As[r][lcol + 1] = tf32r(pa[i].y);
            As[r][lcol + 2] = tf32r(pa[i].z);
            As[r][lcol + 3] = tf32r(pa[i].w);
            Bs[r][lcol + 0] = tf32r(pb[i].x);
            Bs[r][lcol + 1] = tf32r(pb[i].y);
            Bs[r][lcol + 2] = tf32r(pb[i].z);
            Bs[r][lcol + 3] = tf32r(pb[i].w);
        }
        __syncthreads();

        if (kc + 1 < NC) {
            const float* An = Ab + (kc + 1) * 32;
            const float* Bn = Bb + (kc + 1) * 32;
            #pragma unroll
            for (int i = 0; i < 4; i++) {
                pa[i] = *(const float4*)(An + (size_t)(lrow + i * 32) * K + lcol);
                pb[i] = *(const float4*)(Bn + (size_t)(lrow + i * 32) * K + lcol);
            }
        }

        #pragma unroll
        for (int ks = 0; ks < 4; ks++) {
            const int k0 = ks * 8;
            uint32_t a[2][4];
            #pragma unroll
            for (int mi = 0; mi < 2; mi++) {
                const int r = wm + mi * 16 + qr;
                a[mi][0] = __float_as_uint(As[r][k0 + qc]);
                a[mi][1] = __float_as_uint(As[r + 8][k0 + qc]);
                a[mi][2] = __float_as_uint(As[r][k0 + qc + 4]);
                a[mi][3] = __float_as_uint(As[r + 8][k0 + qc + 4]);
            }
            #pragma unroll
            for (int ni = 0; ni < 8; ni++) {
                const int rn = wn + ni * 8 + qr;
                const uint32_t b0 = __float_as_uint(Bs[rn][k0 + qc]);
                const uint32_t b1 = __float_as_uint(Bs[rn][k0 + qc + 4]);
                mma8(acc[0][ni], a[0][0], a[0][1], a[0][2], a[0][3], b0, b1);
                mma8(acc[1][ni], a[1][0], a[1][1], a[1][2], a[1][3], b0, b1);
            }
        }
        __syncthreads();
    }

    // epilogue
    #pragma unroll
    for (int mi = 0; mi < 2; mi++) {
        const int rbase = by * 128 + wm + mi * 16 + qr;
        #pragma unroll
        for (int half = 0; half < 2; half++) {
            const int row = rbase + half * 8;
            float* Cp = C + (size_t)row * N + bx * 128 + wn;
            const float* bp = bias + bx * 128 + wn;
            #pragma unroll
            for (int ni = 0; ni < 8; ni++) {
                const int c = ni * 8 + 2 * qc;
                float2 v;
                v.x = acc[mi][ni][half * 2 + 0] + bp[c];
                v.y = acc[mi][ni][half * 2 + 1] + bp[c + 1];
                *(float2*)(Cp + c) = v;
            }
        }
    }
}

// ---------------------------------------------------------------------------
// Kernel 3: flash attention with tf32 mma.  BR=BC=64, d=64.
// 128 threads = 4 warps; each warp owns 16 full query rows, so the online
// softmax is warp-local (quad shfl reductions).  P goes through warp-private
// SMEM to convert C-fragment layout to A-fragment layout.
// ---------------------------------------------------------------------------
#define QSTR 68   // ≡4 mod 32: conflict-free for the 4r+c A/B patterns
#define VSTR 72   // ≡8 mod 32: conflict-free for the V b-frag pattern

__global__ __launch_bounds__(128) void flash_mma(
    const float* __restrict__ qkv, float* __restrict__ out)
{
    extern __shared__ float fsm[];
    float (*Qs)[QSTR] = (float(*)[QSTR])(fsm);
    float (*Ks)[QSTR] = (float(*)[QSTR])(fsm + 64 * QSTR);
    float (*Ps)[QSTR] = (float(*)[QSTR])(fsm + 2 * 64 * QSTR);
    float (*Vs)[VSTR] = (float(*)[VSTR])(fsm + 3 * 64 * QSTR);

    const int tid  = threadIdx.x;
    const int lane = tid & 31;
    const int wid  = tid >> 5;       // 0..3
    const int qr = lane >> 2;        // 0..7
    const int qc = lane & 3;         // 0..3
    const int m0 = wid * 16;

    const int qt = blockIdx.x;       // query tile 0..31
    const int bh = blockIdx.y;       // 0..47
    const int bb = bh / HEADS, h = bh % HEADS;

    const float* base = qkv + (size_t)bb * SEQ * QKV_N;
    const float* qb = base + h * DHEAD;
    const float* kb = base + INNER + h * DHEAD;
    const float* vb = base + 2 * INNER + h * DHEAD;

    // load Q tile (scaled by 1/sqrt(64), tf32-rounded)
    for (int i = tid; i < 1024; i += 128) {
        const int r = i >> 4, c4 = (i & 15) << 2;
        float4 q = *(const float4*)(qb + (size_t)(qt * 64 + r) * QKV_N + c4);
        *(float4*)&Qs[r][c4] = make_float4(tf32r(q.x * 0.125f), tf32r(q.y * 0.125f),
                                           tf32r(q.z * 0.125f), tf32r(q.w * 0.125f));
    }

    float mrow[2] = {-1e30f, -1e30f};
    float lrow[2] = {0.f, 0.f};
    float o[8][4];
    #pragma unroll
    for (int ni = 0; ni < 8; ni++)
        #pragma unroll
        for (int j = 0; j < 4; j++) o[ni][j] = 0.f;

    for (int t = 0; t < SEQ / 64; t++) {
        __syncthreads();
        for (int i = tid; i < 1024; i += 128) {
            const int r = i >> 4, c4 = (i & 15) << 2;
            const size_t off = (size_t)(t * 64 + r) * QKV_N + c4;
            float4 k = *(const float4*)(kb + off);
            *(float4*)&Ks[r][c4] = make_float4(tf32r(k.x), tf32r(k.y),
                                               tf32r(k.z), tf32r(k.w));
            float4 v = *(const float4*)(vb + off);
            *(float4*)&Vs[r][c4] = make_float4(tf32r(v.x), tf32r(v.y),
                                               tf32r(v.z), tf32r(v.w));
        }
        __syncthreads();

        // ---- S = Q @ K^T ----
        float s[8][4];
        #pragma unroll
        for (int ni = 0; ni < 8; ni++)
            #pragma unroll
            for (int j = 0; j < 4; j++) s[ni][j] = 0.f;

        #pragma unroll
        for (int ks = 0; ks < 8; ks++) {
            const int k0 = ks * 8;
            const uint32_t a0 = __float_as_uint(Qs[m0 + qr][k0 + qc]);
            const uint32_t a1 = __float_as_uint(Qs[m0 + qr + 8][k0 + qc]);
            const uint32_t a2 = __float_as_uint(Qs[m0 + qr][k0 + qc + 4]);
            const uint32_t a3 = __float_as_uint(Qs[m0 + qr + 8][k0 + qc + 4]);
            #pragma unroll
            for (int ni = 0; ni < 8; ni++) {
                const uint32_t b0 = __float_as_uint(Ks[ni * 8 + qr][k0 + qc]);
                const uint32_t b1 = __float_as_uint(Ks[ni * 8 + qr][k0 + qc + 4]);
                mma8(s[ni], a0, a1, a2, a3, b0, b1);
            }
        }

        // ---- online softmax (rows lane/4 and lane/4+8; quad reductions) ----
        float mx0 = -1e30f, mx1 = -1e30f;
        #pragma unroll
        for (int ni = 0; ni < 8; ni++) {
            mx0 = fmaxf(mx0, fmaxf(s[ni][0], s[ni][1]));
            mx1 = fmaxf(mx1, fmaxf(s[ni][2], s[ni][3]));
        }
        mx0 = fmaxf(mx0, __shfl_xor_sync(0xffffffffu, mx0, 1));
        mx0 = fmaxf(mx0, __shfl_xor_sync(0xffffffffu, mx0, 2));
        mx1 = fmaxf(mx1, __shfl_xor_sync(0xffffffffu, mx1, 1));
        mx1 = fmaxf(mx1, __shfl_xor_sync(0xffffffffu, mx1, 2));

        const float mn0 = fmaxf(mrow[0], mx0);
        const float mn1 = fmaxf(mrow[1], mx1);
        const float al0 = __expf(mrow[0] - mn0);
        const float al1 = __expf(mrow[1] - mn1);
        mrow[0] = mn0; mrow[1] = mn1;

        float sum0 = 0.f, sum1 = 0.f;
        #pragma unroll
        for (int ni = 0; ni < 8; ni++) {
            s[ni][0] = __expf(s[ni][0] - mn0); sum0 += s[ni][0];
            s[ni][1] = __expf(s[ni][1] - mn0); sum0 += s[ni][1];
            s[ni][2] = __expf(s[ni][2] - mn1); sum1 += s[ni][2];
            s[ni][3] = __expf(s[ni][3] - mn1); sum1 += s[ni][3];
        }
        sum0 += __shfl_xor_sync(0xffffffffu, sum0, 1);
        sum0 += __shfl_xor_sync(0xffffffffu, sum0, 2);
        sum1 += __shfl_xor_sync(0xffffffffu, sum1, 1);
        sum1 += __shfl_xor_sync(0xffffffffu, sum1, 2);
        lrow[0] = lrow[0] * al0 + sum0;
        lrow[1] = lrow[1] * al1 + sum1;

        #pragma unroll
        for (int ni = 0; ni < 8; ni++) {
            o[ni][0] *= al0; o[ni][1] *= al0;
            o[ni][2] *= al1; o[ni][3] *= al1;
        }

        // ---- P (C-frag) -> warp-private SMEM (A-frag source) ----
        #pragma unroll
        for (int ni = 0; ni < 8; ni++) {
            const int c = ni * 8 + 2 * qc;
            Ps[m0 + qr][c]         = tf32r(s[ni][0]);
            Ps[m0 + qr][c + 1]     = tf32r(s[ni][1]);
            Ps[m0 + qr + 8][c]     = tf32r(s[ni][2]);
            Ps[m0 + qr + 8][c + 1] = tf32r(s[ni][3]);
        }
        __syncwarp();

        // ---- O += P @ V ----
        #pragma unroll
        for (int ks = 0; ks < 8; ks++) {
            const int k0 = ks * 8;
            const uint32_t a0 = __float_as_uint(Ps[m0 + qr][k0 + qc]);
            const uint32_t a1 = __float_as_uint(Ps[m0 + qr + 8][k0 + qc]);
            const uint32_t a2 = __float_as_uint(Ps[m0 + qr][k0 + qc + 4]);
            const uint32_t a3 = __float_as_uint(Ps[m0 + qr + 8][k0 + qc + 4]);
            #pragma unroll
            for (int ni = 0; ni < 8; ni++) {
                const uint32_t b0 = __float_as_uint(Vs[k0 + qc][ni * 8 + qr]);
                const uint32_t b1 = __float_as_uint(Vs[k0 + qc + 4][ni * 8 + qr]);
                mma8(o[ni], a0, a1, a2, a3, b0, b1);
            }
        }
        __syncwarp();
    }

    // ---- normalize + store ([b, n, h*64 + d]) ----
    const float inv0 = 1.f / lrow[0];
    const float inv1 = 1.f / lrow[1];
    const size_t n0 = (size_t)bb * SEQ + qt * 64 + m0 + qr;
    #pragma unroll
    for (int ni = 0; ni < 8; ni++) {
        const int c = h * DHEAD + ni * 8 + 2 * qc;
        float2 v0; v0.x = o[ni][0] * inv0; v0.y = o[ni][1] * inv0;
        *(float2*)(out + n0 * INNER + c) = v0;
        float2 v1; v1.x = o[ni][2] * inv1; v1.y = o[ni][3] * inv1;
        *(float2*)(out + (n0 + 8) * INNER + c) = v1;
    }
}

// ---------------------------------------------------------------------------
extern "C" void kernel_launch(void* const* d_in, const int* in_sizes, int n_in,
                              void* d_out, int out_size)
{
    const float* x     = (const float*)d_in[0];
    const float* ln_g  = (const float*)d_in[1];
    const float* ln_b  = (const float*)d_in[2];
    const float* W_qkv = (const float*)d_in[3];
    const float* b_qkv = (const float*)d_in[4];
    const float* W_out = (const float*)d_in[5];
    const float* b_out = (const float*)d_in[6];
    float* out = (float*)d_out;

    float *xn, *qkv, *attn, *wtq, *wto;
    cudaGetSymbolAddress((void**)&xn,   g_xn);
    cudaGetSymbolAddress((void**)&qkv,  g_qkv);
    cudaGetSymbolAddress((void**)&attn, g_attn);
    cudaGetSymbolAddress((void**)&wtq,  g_wtq);
    cudaGetSymbolAddress((void**)&wto,  g_wto);

    const int flash_smem = (3 * 64 * QSTR + 64 * VSTR) * (int)sizeof(float);
    cudaFuncSetAttribute(flash_mma, cudaFuncAttributeMaxDynamicSharedMemorySize,
                         flash_smem);

    // 0) transpose weights to [N,K]
    transpose_k<<<dim3(QKV_N / 32, DIM / 32), 256>>>(W_qkv, wtq, DIM, QKV_N);
    transpose_k<<<dim3(DIM / 32, INNER / 32), 256>>>(W_out, wto, INNER, DIM);

    // 1) LayerNorm
    ln_kernel<<<ROWS, 256>>>(x, ln_g, ln_b, xn);

    // 2) QKV projection (tf32 mma): [8192,768] @ [768,2304] + b
    gemm_mma<<<dim3(QKV_N / 128, ROWS / 128), 256>>>(xn, wtq, b_qkv, qkv,
                                                     QKV_N, DIM);

    // 3) attention (tf32 mma flash)
    flash_mma<<<dim3(SEQ / 64, BATCH * HEADS), 128, flash_smem>>>(qkv, attn);

    // 4) output projection (tf32 mma): [8192,768] @ [768,768] + b
    gemm_mma<<<dim3(DIM / 128, ROWS / 128), 256>>>(attn, wto, b_out, out,
                                                   DIM, INNER);
}

// round 7
// speedup vs baseline: 7.5382x; 2.1930x over previous
#include <cuda_runtime.h>
#include <cuda_fp16.h>
#include <cstdint>
#include <math.h>

// Problem constants
#define BATCH 4
#define SEQ   2048
#define DIM   768
#define HEADS 12
#define DHEAD 64
#define INNER 768
#define ROWS  (BATCH * SEQ)        // 8192
#define QKV_N (3 * INNER)          // 2304

// Scratch (allocation-free: __device__ globals) — all intermediates fp16
__device__ __align__(256) __half g_xn[ROWS * DIM];
__device__ __align__(256) __half g_qkv[ROWS * QKV_N];
__device__ __align__(256) __half g_attn[ROWS * INNER];
__device__ __align__(256) __half g_wtq[QKV_N * DIM];   // W_qkv^T [N,K]
__device__ __align__(256) __half g_wto[DIM * INNER];   // W_out^T [N,K]

// ---------------------------------------------------------------------------
// helpers (all plain sm_80-era PTX — compiles for bare compute_103)
// ---------------------------------------------------------------------------
__device__ __forceinline__ uint32_t smem_u32(const void* p) {
    uint32_t a;
    asm("{ .reg .u64 t; cvta.to.shared.u64 t, %1; cvt.u32.u64 %0, t; }"
        : "=r"(a) : "l"(p));
    return a;
}

__device__ __forceinline__ void cp16(uint32_t dst, const void* src) {
    asm volatile("cp.async.cg.shared.global [%0], [%1], 16;"
                 :: "r"(dst), "l"(src));
}
#define CP_COMMIT() asm volatile("cp.async.commit_group;")
#define CP_WAIT0()  asm volatile("cp.async.wait_group 0;")
#define CP_WAIT1()  asm volatile("cp.async.wait_group 1;")

__device__ __forceinline__ void ldm4(uint32_t r[4], uint32_t a) {
    asm volatile("ldmatrix.sync.aligned.m8n8.x4.shared.b16 {%0,%1,%2,%3}, [%4];"
        : "=r"(r[0]), "=r"(r[1]), "=r"(r[2]), "=r"(r[3]) : "r"(a));
}
__device__ __forceinline__ void ldm4t(uint32_t r[4], uint32_t a) {
    asm volatile("ldmatrix.sync.aligned.m8n8.x4.trans.shared.b16 {%0,%1,%2,%3}, [%4];"
        : "=r"(r[0]), "=r"(r[1]), "=r"(r[2]), "=r"(r[3]) : "r"(a));
}

__device__ __forceinline__ void mma16(float c[4], const uint32_t a[4],
                                      uint32_t b0, uint32_t b1) {
    asm volatile(
        "mma.sync.aligned.m16n8k16.row.col.f32.f16.f16.f32 "
        "{%0,%1,%2,%3}, {%4,%5,%6,%7}, {%8,%9}, {%0,%1,%2,%3};"
        : "+f"(c[0]), "+f"(c[1]), "+f"(c[2]), "+f"(c[3])
        : "r"(a[0]), "r"(a[1]), "r"(a[2]), "r"(a[3]), "r"(b0), "r"(b1));
}

// ---------------------------------------------------------------------------
// Kernel 0: transpose W[K,N] -> Wt[N,K] (fp16 out)
// ---------------------------------------------------------------------------
__global__ __launch_bounds__(256) void transpose_k(
    const float* __restrict__ W, __half* __restrict__ Wt, int R, int Ccols)
{
    __shared__ float t[32][33];
    const int c0 = blockIdx.x * 32, r0 = blockIdx.y * 32;
    const int x = threadIdx.x & 31, y = threadIdx.x >> 5;
    #pragma unroll
    for (int i = 0; i < 32; i += 8)
        t[y + i][x] = W[(size_t)(r0 + y + i) * Ccols + c0 + x];
    __syncthreads();
    #pragma unroll
    for (int i = 0; i < 32; i += 8)
        Wt[(size_t)(c0 + y + i) * R + r0 + x] = __float2half_rn(t[x][y + i]);
}

// ---------------------------------------------------------------------------
// Kernel 1: LayerNorm (fp16 out)
// ---------------------------------------------------------------------------
__global__ __launch_bounds__(256) void ln_kernel(
    const float* __restrict__ x, const float* __restrict__ g,
    const float* __restrict__ b, __half* __restrict__ xn)
{
    const int row = blockIdx.x;
    const int tid = threadIdx.x;
    const float* xr = x + (size_t)row * DIM;

    float v0 = xr[tid];
    float v1 = xr[tid + 256];
    float v2 = xr[tid + 512];
    float s  = v0 + v1 + v2;
    float ss = v0 * v0 + v1 * v1 + v2 * v2;

    #pragma unroll
    for (int m = 16; m; m >>= 1) {
        s  += __shfl_xor_sync(0xffffffffu, s, m);
        ss += __shfl_xor_sync(0xffffffffu, ss, m);
    }
    __shared__ float shs[8], shss[8], stat[2];
    const int w = tid >> 5, l = tid & 31;
    if (l == 0) { shs[w] = s; shss[w] = ss; }
    __syncthreads();
    if (tid == 0) {
        float S = 0.f, SS = 0.f;
        #pragma unroll
        for (int i = 0; i < 8; i++) { S += shs[i]; SS += shss[i]; }
        float mean = S * (1.f / DIM);
        float var  = SS * (1.f / DIM) - mean * mean;
        stat[0] = mean;
        stat[1] = rsqrtf(var + 1e-5f);
    }
    __syncthreads();
    const float mean = stat[0], rstd = stat[1];
    __half* xo = xn + (size_t)row * DIM;
    xo[tid]       = __float2half_rn((v0 - mean) * rstd * g[tid]       + b[tid]);
    xo[tid + 256] = __float2half_rn((v1 - mean) * rstd * g[tid + 256] + b[tid + 256]);
    xo[tid + 512] = __float2half_rn((v2 - mean) * rstd * g[tid + 512] + b[tid + 512]);
}

// ---------------------------------------------------------------------------
// Kernel 2/4: fp16 mma GEMM.  C[M,N] = A[M,K] @ Bt[N,K]^T + bias
// 128x128 block, 8 warps (4m x 2n), warp 32x64, BK=32, cp.async 2-stage,
// ldmatrix fragments.  SMEM row stride 40 halfs (80B): conflict-free.
// ---------------------------------------------------------------------------
#define GSTR 40

__global__ __launch_bounds__(256) void gemm_h(
    const __half* __restrict__ A, const __half* __restrict__ Bt,
    const float* __restrict__ bias, void* __restrict__ Cout,
    int N, int K, int half_out)
{
    __shared__ __half As[2][128 * GSTR];
    __shared__ __half Bs[2][128 * GSTR];

    const int tid  = threadIdx.x;
    const int lane = tid & 31;
    const int wid  = tid >> 5;
    const int wm = (wid >> 1) * 32;
    const int wn = (wid & 1) * 64;
    const int qr = lane >> 2, qc = lane & 3;
    const int bx = blockIdx.x, by = blockIdx.y;

    const __half* Ab = A  + (size_t)by * 128 * K;
    const __half* Bb = Bt + (size_t)bx * 128 * K;

    float acc[2][8][4];
    #pragma unroll
    for (int mi = 0; mi < 2; mi++)
        #pragma unroll
        for (int ni = 0; ni < 8; ni++)
            #pragma unroll
            for (int j = 0; j < 4; j++) acc[mi][ni][j] = 0.f;

    const int NC = K / 32;

    // ---- stage loader: 128 rows x 32 halfs per operand = 512 x 16B chunks
    const int lr = tid >> 2;          // base row (i>>2 with i=tid)
    const int lc = (tid & 3) * 8;     // col in halfs
    const int lr2 = (tid + 256) >> 2;
    // (lc identical for i and i+256 since 256%4==0)

    {   // prologue: stage 0
        uint32_t au = smem_u32(As[0]);
        uint32_t bu = smem_u32(Bs[0]);
        cp16(au + (uint32_t)(lr  * GSTR + lc) * 2, Ab + (size_t)lr  * K + lc);
        cp16(bu + (uint32_t)(lr  * GSTR + lc) * 2, Bb + (size_t)lr  * K + lc);
        cp16(au + (uint32_t)(lr2 * GSTR + lc) * 2, Ab + (size_t)lr2 * K + lc);
        cp16(bu + (uint32_t)(lr2 * GSTR + lc) * 2, Bb + (size_t)lr2 * K + lc);
        CP_COMMIT();
    }

    for (int kc = 0; kc < NC; kc++) {
        const int buf = kc & 1;
        if (kc + 1 < NC) {
            const int k8 = (kc + 1) * 32;
            uint32_t au = smem_u32(As[buf ^ 1]);
            uint32_t bu = smem_u32(Bs[buf ^ 1]);
            cp16(au + (uint32_t)(lr  * GSTR + lc) * 2, Ab + (size_t)lr  * K + k8 + lc);
            cp16(bu + (uint32_t)(lr  * GSTR + lc) * 2, Bb + (size_t)lr  * K + k8 + lc);
            cp16(au + (uint32_t)(lr2 * GSTR + lc) * 2, Ab + (size_t)lr2 * K + k8 + lc);
            cp16(bu + (uint32_t)(lr2 * GSTR + lc) * 2, Bb + (size_t)lr2 * K + k8 + lc);
            CP_COMMIT();
            CP_WAIT1();
        } else {
            CP_WAIT0();
        }
        __syncthreads();

        const uint32_t a_base = smem_u32(As[buf]);
        const uint32_t b_base = smem_u32(Bs[buf]);
        #pragma unroll
        for (int ks = 0; ks < 2; ks++) {
            const int k0 = ks * 16;
            uint32_t af[2][4];
            #pragma unroll
            for (int mi = 0; mi < 2; mi++) {
                const uint32_t ad = a_base +
                    (uint32_t)((wm + mi * 16 + (lane & 15)) * GSTR
                               + k0 + ((lane >> 4) << 3)) * 2;
                ldm4(af[mi], ad);
            }
            #pragma unroll
            for (int np = 0; np < 4; np++) {
                uint32_t bf[4];
                const uint32_t bd = b_base +
                    (uint32_t)((wn + np * 16 + (lane & 7) + ((lane >> 4) << 3)) * GSTR
                               + k0 + (((lane >> 3) & 1) << 3)) * 2;
                ldm4(bf, bd);
                mma16(acc[0][2 * np],     af[0], bf[0], bf[1]);
                mma16(acc[0][2 * np + 1], af[0], bf[2], bf[3]);
                mma16(acc[1][2 * np],     af[1], bf[0], bf[1]);
                mma16(acc[1][2 * np + 1], af[1], bf[2], bf[3]);
            }
        }
        __syncthreads();
    }

    // ---- epilogue
    const int cb = bx * 128 + wn;
    if (half_out) {
        __half* C = (__half*)Cout;
        #pragma unroll
        for (int mi = 0; mi < 2; mi++)
            #pragma unroll
            for (int hf = 0; hf < 2; hf++) {
                const int row = by * 128 + wm + mi * 16 + qr + hf * 8;
                __half* Cp = C + (size_t)row * N + cb;
                #pragma unroll
                for (int ni = 0; ni < 8; ni++) {
                    const int c = ni * 8 + 2 * qc;
                    *(__half2*)(Cp + c) = __floats2half2_rn(
                        acc[mi][ni][hf * 2 + 0] + bias[cb + c],
                        acc[mi][ni][hf * 2 + 1] + bias[cb + c + 1]);
                }
            }
    } else {
        float* C = (float*)Cout;
        #pragma unroll
        for (int mi = 0; mi < 2; mi++)
            #pragma unroll
            for (int hf = 0; hf < 2; hf++) {
                const int row = by * 128 + wm + mi * 16 + qr + hf * 8;
                float* Cp = C + (size_t)row * N + cb;
                #pragma unroll
                for (int ni = 0; ni < 8; ni++) {
                    const int c = ni * 8 + 2 * qc;
                    float2 v;
                    v.x = acc[mi][ni][hf * 2 + 0] + bias[cb + c];
                    v.y = acc[mi][ni][hf * 2 + 1] + bias[cb + c + 1];
                    *(float2*)(Cp + c) = v;
                }
            }
    }
}

// ---------------------------------------------------------------------------
// Kernel 3: fp16 flash attention.  BR=BC=64, d=64.  4 warps; warp owns 16
// query rows (warp-local online softmax).  cp.async double-buffered K/V.
// PV B-operand via ldmatrix.trans directly from row-major V.
// ---------------------------------------------------------------------------
#define FSTR 72

__global__ __launch_bounds__(128) void flash_h(
    const __half* __restrict__ qkv, __half* __restrict__ out)
{
    extern __shared__ __half fs[];
    __half* Qs = fs;
    __half* Ps = fs + 64 * FSTR;
    __half* Kst[2] = { fs + 2 * 64 * FSTR, fs + 3 * 64 * FSTR };
    __half* Vst[2] = { fs + 4 * 64 * FSTR, fs + 5 * 64 * FSTR };

    const int tid  = threadIdx.x;
    const int lane = tid & 31;
    const int wid  = tid >> 5;
    const int qr = lane >> 2, qc = lane & 3;
    const int m0 = wid * 16;

    const int qt = blockIdx.x;
    const int bh = blockIdx.y;
    const int bb = bh / HEADS, h = bh % HEADS;

    const __half* base = qkv + (size_t)bb * SEQ * QKV_N;
    const __half* qb = base + h * DHEAD;
    const __half* kb = base + INNER + h * DHEAD;
    const __half* vb = base + 2 * INNER + h * DHEAD;

    const uint32_t q_u = smem_u32(Qs);
    const uint32_t p_u = smem_u32(Ps);
    const uint32_t k_u[2] = { smem_u32(Kst[0]), smem_u32(Kst[1]) };
    const uint32_t v_u[2] = { smem_u32(Vst[0]), smem_u32(Vst[1]) };

    // prologue: Q tile + K/V stage 0 (one group)
    #pragma unroll
    for (int j = 0; j < 4; j++) {
        const int i = tid + j * 128;           // 0..511
        const int r = i >> 3, cg = (i & 7) * 8;
        cp16(q_u + (uint32_t)(r * FSTR + cg) * 2,
             qb + (size_t)(qt * 64 + r) * QKV_N + cg);
    }
    #pragma unroll
    for (int j = 0; j < 4; j++) {
        const int i = tid + j * 128;
        const int r = i >> 3, cg = (i & 7) * 8;
        const size_t off = (size_t)r * QKV_N + cg;
        cp16(k_u[0] + (uint32_t)(r * FSTR + cg) * 2, kb + off);
        cp16(v_u[0] + (uint32_t)(r * FSTR + cg) * 2, vb + off);
    }
    CP_COMMIT();

    float mrow[2] = {-1e30f, -1e30f};
    float lrow[2] = {0.f, 0.f};
    float o[8][4];
    #pragma unroll
    for (int ni = 0; ni < 8; ni++)
        #pragma unroll
        for (int j = 0; j < 4; j++) o[ni][j] = 0.f;

    uint32_t qf[4][4];
    const int NT = SEQ / 64;

    for (int t = 0; t < NT; t++) {
        const int buf = t & 1;
        if (t + 1 < NT) {
            #pragma unroll
            for (int j = 0; j < 4; j++) {
                const int i = tid + j * 128;
                const int r = i >> 3, cg = (i & 7) * 8;
                const size_t off = (size_t)((t + 1) * 64 + r) * QKV_N + cg;
                cp16(k_u[buf ^ 1] + (uint32_t)(r * FSTR + cg) * 2, kb + off);
                cp16(v_u[buf ^ 1] + (uint32_t)(r * FSTR + cg) * 2, vb + off);
            }
            CP_COMMIT();
            CP_WAIT1();
        } else {
            CP_WAIT0();
        }
        __syncthreads();

        if (t == 0) {
            #pragma unroll
            for (int ks = 0; ks < 4; ks++)
                ldm4(qf[ks], q_u + (uint32_t)((m0 + (lane & 15)) * FSTR
                         + ks * 16 + ((lane >> 4) << 3)) * 2);
        }

        // ---- S = Q @ K^T ----
        float s[8][4];
        #pragma unroll
        for (int ni = 0; ni < 8; ni++)
            #pragma unroll
            for (int j = 0; j < 4; j++) s[ni][j] = 0.f;

        #pragma unroll
        for (int ks = 0; ks < 4; ks++) {
            const int k0 = ks * 16;
            #pragma unroll
            for (int np = 0; np < 4; np++) {
                uint32_t bf[4];
                const uint32_t bd = k_u[buf] +
                    (uint32_t)((np * 16 + (lane & 7) + ((lane >> 4) << 3)) * FSTR
                               + k0 + (((lane >> 3) & 1) << 3)) * 2;
                ldm4(bf, bd);
                mma16(s[2 * np],     qf[ks], bf[0], bf[1]);
                mma16(s[2 * np + 1], qf[ks], bf[2], bf[3]);
            }
        }

        // ---- scale + online softmax (quad reductions) ----
        #pragma unroll
        for (int ni = 0; ni < 8; ni++)
            #pragma unroll
            for (int j = 0; j < 4; j++) s[ni][j] *= 0.125f;

        float mx0 = -1e30f, mx1 = -1e30f;
        #pragma unroll
        for (int ni = 0; ni < 8; ni++) {
            mx0 = fmaxf(mx0, fmaxf(s[ni][0], s[ni][1]));
            mx1 = fmaxf(mx1, fmaxf(s[ni][2], s[ni][3]));
        }
        mx0 = fmaxf(mx0, __shfl_xor_sync(0xffffffffu, mx0, 1));
        mx0 = fmaxf(mx0, __shfl_xor_sync(0xffffffffu, mx0, 2));
        mx1 = fmaxf(mx1, __shfl_xor_sync(0xffffffffu, mx1, 1));
        mx1 = fmaxf(mx1, __shfl_xor_sync(0xffffffffu, mx1, 2));

        const float mn0 = fmaxf(mrow[0], mx0);
        const float mn1 = fmaxf(mrow[1], mx1);
        const float al0 = __expf(mrow[0] - mn0);
        const float al1 = __expf(mrow[1] - mn1);
        mrow[0] = mn0; mrow[1] = mn1;

        float sum0 = 0.f, sum1 = 0.f;
        #pragma unroll
        for (int ni = 0; ni < 8; ni++) {
            s[ni][0] = __expf(s[ni][0] - mn0); sum0 += s[ni][0];
            s[ni][1] = __expf(s[ni][1] - mn0); sum0 += s[ni][1];
            s[ni][2] = __expf(s[ni][2] - mn1); sum1 += s[ni][2];
            s[ni][3] = __expf(s[ni][3] - mn1); sum1 += s[ni][3];
        }
        sum0 += __shfl_xor_sync(0xffffffffu, sum0, 1);
        sum0 += __shfl_xor_sync(0xffffffffu, sum0, 2);
        sum1 += __shfl_xor_sync(0xffffffffu, sum1, 1);
        sum1 += __shfl_xor_sync(0xffffffffu, sum1, 2);
        lrow[0] = lrow[0] * al0 + sum0;
        lrow[1] = lrow[1] * al1 + sum1;

        #pragma unroll
        for (int ni = 0; ni < 8; ni++) {
            o[ni][0] *= al0; o[ni][1] *= al0;
            o[ni][2] *= al1; o[ni][3] *= al1;
        }

        // ---- P (C-frag, fp32) -> warp-private SMEM as fp16 ----
        #pragma unroll
        for (int ni = 0; ni < 8; ni++) {
            const int c = ni * 8 + 2 * qc;
            *(__half2*)(Ps + (m0 + qr) * FSTR + c) =
                __floats2half2_rn(s[ni][0], s[ni][1]);
            *(__half2*)(Ps + (m0 + qr + 8) * FSTR + c) =
                __floats2half2_rn(s[ni][2], s[ni][3]);
        }
        __syncwarp();

        // ---- O += P @ V  (V via ldmatrix.trans) ----
        #pragma unroll
        for (int ks = 0; ks < 4; ks++) {
            uint32_t pf[4];
            ldm4(pf, p_u + (uint32_t)((m0 + (lane & 15)) * FSTR
                     + ks * 16 + ((lane >> 4) << 3)) * 2);
            #pragma unroll
            for (int np = 0; np < 4; np++) {
                uint32_t vf[4];
                const uint32_t vd = v_u[buf] +
                    (uint32_t)((ks * 16 + (lane & 7) + (((lane >> 3) & 1) << 3)) * FSTR
                               + np * 16 + ((lane >> 4) << 3)) * 2;
                ldm4t(vf, vd);
                mma16(o[2 * np],     pf, vf[0], vf[1]);
                mma16(o[2 * np + 1], pf, vf[2], vf[3]);
            }
        }
        __syncwarp();
        __syncthreads();   // protect K/V buf against next prefetch overwrite
    }

    // ---- normalize + store (half) into [b, n, h*64 + d] ----
    const float inv0 = 1.f / lrow[0];
    const float inv1 = 1.f / lrow[1];
    const size_t n0 = (size_t)bb * SEQ + qt * 64 + m0 + qr;
    #pragma unroll
    for (int ni = 0; ni < 8; ni++) {
        const int c = h * DHEAD + ni * 8 + 2 * qc;
        *(__half2*)(out + n0 * INNER + c) =
            __floats2half2_rn(o[ni][0] * inv0, o[ni][1] * inv0);
        *(__half2*)(out + (n0 + 8) * INNER + c) =
            __floats2half2_rn(o[ni][2] * inv1, o[ni][3] * inv1);
    }
}

// ---------------------------------------------------------------------------
extern "C" void kernel_launch(void* const* d_in, const int* in_sizes, int n_in,
                              void* d_out, int out_size)
{
    const float* x     = (const float*)d_in[0];
    const float* ln_g  = (const float*)d_in[1];
    const float* ln_b  = (const float*)d_in[2];
    const float* W_qkv = (const float*)d_in[3];
    const float* b_qkv = (const float*)d_in[4];
    const float* W_out = (const float*)d_in[5];
    const float* b_out = (const float*)d_in[6];
    float* out = (float*)d_out;

    __half *xn, *qkv, *attn, *wtq, *wto;
    cudaGetSymbolAddress((void**)&xn,   g_xn);
    cudaGetSymbolAddress((void**)&qkv,  g_qkv);
    cudaGetSymbolAddress((void**)&attn, g_attn);
    cudaGetSymbolAddress((void**)&wtq,  g_wtq);
    cudaGetSymbolAddress((void**)&wto,  g_wto);

    const int flash_smem = 6 * 64 * FSTR * (int)sizeof(__half);  // 55296
    cudaFuncSetAttribute(flash_h, cudaFuncAttributeMaxDynamicSharedMemorySize,
                         flash_smem);

    // 0) transpose weights to [N,K] fp16
    transpose_k<<<dim3(QKV_N / 32, DIM / 32), 256>>>(W_qkv, wtq, DIM, QKV_N);
    transpose_k<<<dim3(DIM / 32, INNER / 32), 256>>>(W_out, wto, INNER, DIM);

    // 1) LayerNorm -> fp16
    ln_kernel<<<ROWS, 256>>>(x, ln_g, ln_b, xn);

    // 2) QKV projection (fp16 mma, half out)
    gemm_h<<<dim3(QKV_N / 128, ROWS / 128), 256>>>(
        xn, wtq, b_qkv, qkv, QKV_N, DIM, 1);

    // 3) attention (fp16 flash, half out)
    flash_h<<<dim3(SEQ / 64, BATCH * HEADS), 128, flash_smem>>>(qkv, attn);

    // 4) output projection (fp16 mma, fp32 out)
    gemm_h<<<dim3(DIM / 128, ROWS / 128), 256>>>(
        attn, wto, b_out, out, DIM, INNER, 0);
}